// round 7
// baseline (speedup 1.0000x reference)
#include <cuda_runtime.h>
#include <math.h>

#define NNODES 50000
#define NEDGES 800000

// ---------------- scratch (device globals: allocation-free) ----------------
__device__ int   g_cnt[NNODES];
__device__ int   g_cursor[NNODES];
__device__ int   g_rowptr[NNODES + 1];
__device__ int   g_colp[NEDGES];
__device__ float g_simp[NEDGES];
__device__ float g_invn[NNODES];
__device__ float g_invrs[NNODES];
__device__ float g_wself[NNODES];
__device__ float g_z [NNODES * 256];
__device__ float g_h1[NNODES * 256];
__device__ float g_h2[NNODES * 256];
__device__ float g_B [256 * 256];

// ---------------- CSR build ----------------
__global__ void zero_cnt_kernel() {
    int i = blockIdx.x * blockDim.x + threadIdx.x;
    if (i < NNODES) g_cnt[i] = 0;
}

__global__ void hist_kernel(const int* __restrict__ row) {
    int e = blockIdx.x * blockDim.x + threadIdx.x;
    if (e < NEDGES) atomicAdd(&g_cnt[row[e]], 1);
}

__global__ void scan_kernel() {
    __shared__ int wsum[32];
    __shared__ int carry;
    int tid = threadIdx.x, lane = tid & 31, wid = tid >> 5;
    if (tid == 0) { carry = 0; g_rowptr[0] = 0; }
    __syncthreads();
    for (int base = 0; base < NNODES; base += 1024) {
        int i = base + tid;
        int v = (i < NNODES) ? g_cnt[i] : 0;
        int s = v;
        #pragma unroll
        for (int o = 1; o < 32; o <<= 1) {
            int t = __shfl_up_sync(0xffffffffu, s, o);
            if (lane >= o) s += t;
        }
        if (lane == 31) wsum[wid] = s;
        __syncthreads();
        if (wid == 0) {
            int ws = wsum[lane];
            #pragma unroll
            for (int o = 1; o < 32; o <<= 1) {
                int t = __shfl_up_sync(0xffffffffu, ws, o);
                if (lane >= o) ws += t;
            }
            wsum[lane] = ws;
        }
        __syncthreads();
        int incl = s + (wid ? wsum[wid - 1] : 0) + carry;
        if (i < NNODES) { g_rowptr[i + 1] = incl; g_cursor[i] = incl - v; }
        __syncthreads();
        if (tid == 1023) carry = incl;
        __syncthreads();
    }
}

__global__ void scatter_kernel(const int* __restrict__ row, const int* __restrict__ col) {
    int e = blockIdx.x * blockDim.x + threadIdx.x;
    if (e >= NEDGES) return;
    int r = row[e];
    int pos = atomicAdd(&g_cursor[r], 1);
    g_colp[pos] = col[e];
}

// ---------------- per-layer kernels ----------------
// repack W[h, d, o] -> B[d, h*HID+o]  (dense [D x Hout] row-major)
__global__ void repack_kernel(const float* __restrict__ W, int D, int Hout, int HIDp) {
    int idx = blockIdx.x * blockDim.x + threadIdx.x;
    if (idx >= D * Hout) return;
    int d = idx / Hout, c = idx % Hout;
    int h = c / HIDp, o = c % HIDp;
    g_B[idx] = W[((size_t)h * D + d) * HIDp + o];
}

// 1 / max(||x_n||, 1e-12), warp per node
__global__ void invn_kernel(const float* __restrict__ x, int D) {
    int n = (blockIdx.x * blockDim.x + threadIdx.x) >> 5;
    int lane = threadIdx.x & 31;
    if (n >= NNODES) return;
    const float4* xr = (const float4*)(x + (size_t)n * D);
    int nq = D >> 2;
    float s = 0.f;
    for (int j = lane; j < nq; j += 32) {
        float4 a = xr[j];
        s += a.x * a.x + a.y * a.y + a.z * a.z + a.w * a.w;
    }
    #pragma unroll
    for (int o = 16; o; o >>= 1) s += __shfl_xor_sync(0xffffffffu, s, o);
    if (lane == 0) g_invn[n] = 1.f / fmaxf(sqrtf(s), 1e-12f);
}

// Group-parallel row-stationary sim: warp per node; G = D/32 lanes cooperate
// per edge, so one warp processes 32/G edges concurrently. Each lane holds 8
// interleaved float4s of the row vector in registers (float4 index lg + j*G),
// so a group's loads at step j are G*16B contiguous (full sectors). Reduction
// is log2(G) xor-shfls per edge instead of 5 — kills the per-edge butterfly
// latency and exposes 8 independent LDG.128 per iteration.
template <int G>
__global__ void sim_group_kernel(const float* __restrict__ x) {
    constexpr int D = G * 32;           // G=4 -> D=128, G=8 -> D=256
    constexpr int NGRP = 32 / G;        // edges in flight per warp
    int n = (blockIdx.x * blockDim.x + threadIdx.x) >> 5;
    int lane = threadIdx.x & 31;
    if (n >= NNODES) return;
    int lg  = lane & (G - 1);           // lane within group
    int grp = lane / G;                 // group id within warp

    const float4* xr = (const float4*)(x + (size_t)n * D);
    float4 r[8];
    #pragma unroll
    for (int j = 0; j < 8; j++) r[j] = xr[lg + j * G];

    float invn_n = g_invn[n];
    int e0 = g_rowptr[n], e1 = g_rowptr[n + 1];
    for (int base = e0; base < e1; base += NGRP) {
        int e = base + grp;
        bool valid = (e < e1);
        int c = valid ? g_colp[e] : n;
        const float4* xc = (const float4*)(x + (size_t)c * D);
        float s = 0.f;
        #pragma unroll
        for (int j = 0; j < 8; j++) {
            float4 b = xc[lg + j * G];
            s += r[j].x * b.x + r[j].y * b.y + r[j].z * b.z + r[j].w * b.w;
        }
        #pragma unroll
        for (int o = G / 2; o; o >>= 1) s += __shfl_xor_sync(0xffffffffu, s, o);
        if (valid && lg == 0) {
            s *= invn_n * g_invn[c];
            g_simp[e] = (s < 0.1f) ? 0.f : s;
        }
    }
}

// rowsum / degree / self weight, warp per node
__global__ void rownorm_kernel() {
    int n = (blockIdx.x * blockDim.x + threadIdx.x) >> 5;
    int lane = threadIdx.x & 31;
    if (n >= NNODES) return;
    int s0 = g_rowptr[n], s1 = g_rowptr[n + 1];
    float sum = 0.f;
    int cnt = 0;
    for (int i = s0 + lane; i < s1; i += 32) {
        float v = g_simp[i];
        sum += v;                 // v >= 0 (thresholded cosine), so |v| == v
        cnt += (v != 0.f);
    }
    #pragma unroll
    for (int o = 16; o; o >>= 1) {
        sum += __shfl_xor_sync(0xffffffffu, sum, o);
        cnt += __shfl_xor_sync(0xffffffffu, cnt, o);
    }
    if (lane == 0) {
        g_invrs[n] = (sum > 0.f) ? 1.f / sum : 0.f;
        g_wself[n] = expf(1.f / ((float)cnt + 1.f));
    }
}

// ---------------- 3xTF32 tensor-core GEMM (fp32-accurate) ----------------
__device__ __forceinline__ unsigned f2tf32(float f) {
    unsigned r;
    asm("cvt.rna.tf32.f32 %0, %1;" : "=r"(r) : "f"(f));
    return r;
}

__device__ __forceinline__ void mma_tf32(float c[4], unsigned a0, unsigned a1,
                                         unsigned a2, unsigned a3,
                                         unsigned b0, unsigned b1) {
    asm volatile(
        "mma.sync.aligned.m16n8k8.row.col.f32.tf32.tf32.f32 "
        "{%0,%1,%2,%3}, {%4,%5,%6,%7}, {%8,%9}, {%0,%1,%2,%3};"
        : "+f"(c[0]), "+f"(c[1]), "+f"(c[2]), "+f"(c[3])
        : "r"(a0), "r"(a1), "r"(a2), "r"(a3), "r"(b0), "r"(b1));
}

// C[M, Nc] = A[M, K] * B[K, Nc], BM=128 BN=64 BK=16, 8 warps (warp tile 32x32)
__global__ void __launch_bounds__(256)
mma_gemm_kernel(const float* __restrict__ A, const float* __restrict__ Bw,
                float* __restrict__ C, int M, int K, int Nc) {
    __shared__ unsigned AsHi[128][20];
    __shared__ unsigned AsLo[128][20];
    __shared__ unsigned BsHi[16][68];
    __shared__ unsigned BsLo[16][68];

    int tid = threadIdx.x;
    int lane = tid & 31, w = tid >> 5;
    int wm = w & 3, wn = w >> 2;       // 4 warps in M, 2 in N
    int g = lane >> 2, t = lane & 3;
    int rb = blockIdx.y * 128, cb = blockIdx.x * 64;

    float acc[2][4][4];
    #pragma unroll
    for (int mi = 0; mi < 2; mi++)
        #pragma unroll
        for (int ni = 0; ni < 4; ni++)
            #pragma unroll
            for (int j = 0; j < 4; j++) acc[mi][ni][j] = 0.f;

    for (int k0 = 0; k0 < K; k0 += 16) {
        // A tile 128x16 -> 512 float4, 2 per thread
        #pragma unroll
        for (int f = tid; f < 512; f += 256) {
            int r = f >> 2, kq = f & 3;
            int gr = rb + r;
            float4 v = make_float4(0.f, 0.f, 0.f, 0.f);
            if (gr < M) v = *(const float4*)&A[(size_t)gr * K + k0 + kq * 4];
            float vv[4] = {v.x, v.y, v.z, v.w};
            #pragma unroll
            for (int j = 0; j < 4; j++) {
                unsigned hi = f2tf32(vv[j]);
                AsHi[r][kq * 4 + j] = hi;
                AsLo[r][kq * 4 + j] = f2tf32(vv[j] - __uint_as_float(hi));
            }
        }
        // B tile 16x64 -> 256 float4, 1 per thread
        {
            int r = tid >> 4, nq = tid & 15;
            float4 v = *(const float4*)&Bw[(size_t)(k0 + r) * Nc + cb + nq * 4];
            float vv[4] = {v.x, v.y, v.z, v.w};
            #pragma unroll
            for (int j = 0; j < 4; j++) {
                unsigned hi = f2tf32(vv[j]);
                BsHi[r][nq * 4 + j] = hi;
                BsLo[r][nq * 4 + j] = f2tf32(vv[j] - __uint_as_float(hi));
            }
        }
        __syncthreads();

        #pragma unroll
        for (int kk = 0; kk < 16; kk += 8) {
            unsigned ah[2][4], al[2][4], bh[4][2], bl[4][2];
            #pragma unroll
            for (int mi = 0; mi < 2; mi++) {
                int r0 = wm * 32 + mi * 16 + g;
                ah[mi][0] = AsHi[r0][kk + t];     ah[mi][1] = AsHi[r0 + 8][kk + t];
                ah[mi][2] = AsHi[r0][kk + t + 4]; ah[mi][3] = AsHi[r0 + 8][kk + t + 4];
                al[mi][0] = AsLo[r0][kk + t];     al[mi][1] = AsLo[r0 + 8][kk + t];
                al[mi][2] = AsLo[r0][kk + t + 4]; al[mi][3] = AsLo[r0 + 8][kk + t + 4];
            }
            #pragma unroll
            for (int ni = 0; ni < 4; ni++) {
                int c0 = wn * 32 + ni * 8 + g;
                bh[ni][0] = BsHi[kk + t][c0]; bh[ni][1] = BsHi[kk + t + 4][c0];
                bl[ni][0] = BsLo[kk + t][c0]; bl[ni][1] = BsLo[kk + t + 4][c0];
            }
            #pragma unroll
            for (int mi = 0; mi < 2; mi++)
                #pragma unroll
                for (int ni = 0; ni < 4; ni++) {
                    // 3xTF32: hi*hi + hi*lo + lo*hi ~= fp32 product
                    mma_tf32(acc[mi][ni], ah[mi][0], ah[mi][1], ah[mi][2], ah[mi][3],
                             bh[ni][0], bh[ni][1]);
                    mma_tf32(acc[mi][ni], ah[mi][0], ah[mi][1], ah[mi][2], ah[mi][3],
                             bl[ni][0], bl[ni][1]);
                    mma_tf32(acc[mi][ni], al[mi][0], al[mi][1], al[mi][2], al[mi][3],
                             bh[ni][0], bh[ni][1]);
                }
        }
        __syncthreads();
    }

    #pragma unroll
    for (int mi = 0; mi < 2; mi++) {
        int row = rb + wm * 32 + mi * 16 + g;
        #pragma unroll
        for (int ni = 0; ni < 4; ni++) {
            int colc = cb + wn * 32 + ni * 8 + 2 * t;
            if (row < M)
                *(float2*)&C[(size_t)row * Nc + colc] =
                    make_float2(acc[mi][ni][0], acc[mi][ni][1]);
            if (row + 8 < M)
                *(float2*)&C[(size_t)(row + 8) * Nc + colc] =
                    make_float2(acc[mi][ni][2], acc[mi][ni][3]);
        }
    }
}

// plain tiled SGEMM (kept for the tiny N=16 final projection)
template <int BM, int BN, int BK, int TM, int TN>
__global__ void __launch_bounds__(256)
sgemm_kernel(const float* __restrict__ A, const float* __restrict__ Bw,
             float* __restrict__ C, int M, int K, int Nc) {
    static_assert((BM / TM) * (BN / TN) == 256, "grid of 256 threads");
    __shared__ float As[BK][BM + 4];
    __shared__ float Bs[BK][BN];
    constexpr int TCOLS = BN / TN;
    int tid = threadIdx.x;
    int tr = tid / TCOLS, tc = tid % TCOLS;
    int rb = blockIdx.y * BM, cb = blockIdx.x * BN;
    float acc[TM][TN];
    #pragma unroll
    for (int i = 0; i < TM; i++)
        #pragma unroll
        for (int j = 0; j < TN; j++) acc[i][j] = 0.f;

    for (int k0 = 0; k0 < K; k0 += BK) {
        for (int idx = tid; idx < BM * BK; idx += 256) {
            int r = idx / BK, c = idx % BK;
            int gr = rb + r;
            As[c][r] = (gr < M) ? A[(size_t)gr * K + k0 + c] : 0.f;
        }
        for (int idx = tid; idx < BK * BN; idx += 256) {
            int r = idx / BN, c = idx % BN;
            Bs[r][c] = Bw[(size_t)(k0 + r) * Nc + cb + c];
        }
        __syncthreads();
        #pragma unroll
        for (int k = 0; k < BK; k++) {
            float a[TM], b[TN];
            #pragma unroll
            for (int i = 0; i < TM; i++) a[i] = As[k][tr * TM + i];
            #pragma unroll
            for (int j = 0; j < TN; j++) b[j] = Bs[k][tc * TN + j];
            #pragma unroll
            for (int i = 0; i < TM; i++)
                #pragma unroll
                for (int j = 0; j < TN; j++) acc[i][j] += a[i] * b[j];
        }
        __syncthreads();
    }
    #pragma unroll
    for (int i = 0; i < TM; i++) {
        int gr = rb + tr * TM + i;
        if (gr < M) {
            #pragma unroll
            for (int j = 0; j < TN; j++)
                C[(size_t)gr * Nc + cb + tc * TN + j] = acc[i][j];
        }
    }
}

// aggregation, Hout = 256: warp per node, lane owns 4+4 contiguous cols
__global__ void agg256_kernel(const float* __restrict__ z, float* __restrict__ out, int act) {
    int n = (blockIdx.x * blockDim.x + threadIdx.x) >> 5;
    int lane = threadIdx.x & 31;
    if (n >= NNODES) return;
    const float4* zr = (const float4*)(z + (size_t)n * 256);
    float ws = g_wself[n];
    float4 a0 = zr[lane], a1 = zr[32 + lane];
    a0.x *= ws; a0.y *= ws; a0.z *= ws; a0.w *= ws;
    a1.x *= ws; a1.y *= ws; a1.z *= ws; a1.w *= ws;
    float irs = g_invrs[n];
    int s1 = g_rowptr[n + 1];
    for (int i = g_rowptr[n]; i < s1; ++i) {
        float sv = g_simp[i];
        if (sv == 0.f) continue;
        float w = expf(sv * irs);
        const float4* zc = (const float4*)(z + (size_t)g_colp[i] * 256);
        float4 b0 = zc[lane], b1 = zc[32 + lane];
        a0.x += w * b0.x; a0.y += w * b0.y; a0.z += w * b0.z; a0.w += w * b0.w;
        a1.x += w * b1.x; a1.y += w * b1.y; a1.z += w * b1.z; a1.w += w * b1.w;
    }
    if (act) {
        a0.x = a0.x > 0.f ? a0.x : 0.01f * a0.x;
        a0.y = a0.y > 0.f ? a0.y : 0.01f * a0.y;
        a0.z = a0.z > 0.f ? a0.z : 0.01f * a0.z;
        a0.w = a0.w > 0.f ? a0.w : 0.01f * a0.w;
        a1.x = a1.x > 0.f ? a1.x : 0.01f * a1.x;
        a1.y = a1.y > 0.f ? a1.y : 0.01f * a1.y;
        a1.z = a1.z > 0.f ? a1.z : 0.01f * a1.z;
        a1.w = a1.w > 0.f ? a1.w : 0.01f * a1.w;
    }
    float4* o = (float4*)(out + (size_t)n * 256);
    o[lane] = a0; o[32 + lane] = a1;
}

// aggregation, Hout = 16 (final layer, no activation)
__global__ void agg16_kernel(const float* __restrict__ z, float* __restrict__ out) {
    int n = (blockIdx.x * blockDim.x + threadIdx.x) >> 5;
    int lane = threadIdx.x & 31;
    if (n >= NNODES || lane >= 16) return;
    float acc = g_wself[n] * z[(size_t)n * 16 + lane];
    float irs = g_invrs[n];
    int s1 = g_rowptr[n + 1];
    for (int i = g_rowptr[n]; i < s1; ++i) {
        float sv = g_simp[i];
        if (sv == 0.f) continue;
        acc += expf(sv * irs) * z[(size_t)g_colp[i] * 16 + lane];
    }
    out[(size_t)n * 16 + lane] = acc;
}

// ---------------- host side ----------------
static void run_layer(const float* xin, int D, const float* W, int HIDp, int Hout,
                      float* outp, bool act, float* zp) {
    repack_kernel<<<(D * Hout + 255) / 256, 256>>>(W, D, Hout, HIDp);
    invn_kernel<<<(NNODES + 7) / 8, 256>>>(xin, D);
    if (D == 128) sim_group_kernel<4><<<(NNODES + 7) / 8, 256>>>(xin);
    else          sim_group_kernel<8><<<(NNODES + 7) / 8, 256>>>(xin);
    rownorm_kernel<<<(NNODES + 7) / 8, 256>>>();
    float* Bdev;
    cudaGetSymbolAddress((void**)&Bdev, g_B);
    if (Hout == 256) {
        dim3 grid(256 / 64, (NNODES + 127) / 128);
        mma_gemm_kernel<<<grid, 256>>>(xin, Bdev, zp, NNODES, D, 256);
        agg256_kernel<<<(NNODES + 7) / 8, 256>>>(zp, outp, act ? 1 : 0);
    } else {
        dim3 grid(1, (NNODES + 63) / 64);
        sgemm_kernel<64, 16, 16, 4, 1><<<grid, 256>>>(xin, Bdev, zp, NNODES, D, 16);
        agg16_kernel<<<(NNODES + 7) / 8, 256>>>(zp, outp);
    }
}

extern "C" void kernel_launch(void* const* d_in, const int* in_sizes, int n_in,
                              void* d_out, int out_size) {
    const float* x  = (const float*)d_in[0];
    const float* W0 = (const float*)d_in[1];
    const float* W1 = (const float*)d_in[2];
    const float* W2 = (const float*)d_in[3];
    const int*   row = (const int*)d_in[4];
    const int*   col = (const int*)d_in[5];
    float* out = (float*)d_out;

    float *zp, *h1p, *h2p;
    cudaGetSymbolAddress((void**)&zp,  g_z);
    cudaGetSymbolAddress((void**)&h1p, g_h1);
    cudaGetSymbolAddress((void**)&h2p, g_h2);

    // CSR build (recomputed every call; deterministic work)
    zero_cnt_kernel<<<(NNODES + 255) / 256, 256>>>();
    hist_kernel<<<(NEDGES + 255) / 256, 256>>>(row);
    scan_kernel<<<1, 1024>>>();
    scatter_kernel<<<(NEDGES + 255) / 256, 256>>>(row, col);

    // layer 0: D=128, W0[4,128,64] -> h1[N,256], leaky relu
    run_layer(x,   128, W0, 64, 256, h1p, true,  zp);
    // layer 1: D=256, W1[4,256,64] -> h2[N,256], leaky relu
    run_layer(h1p, 256, W1, 64, 256, h2p, true,  zp);
    // layer 2: D=256, W2[1,256,16] -> out[N,16], no activation
    run_layer(h2p, 256, W2, 16, 16,  out, false, zp);
}

// round 8
// speedup vs baseline: 1.2254x; 1.2254x over previous
#include <cuda_runtime.h>
#include <cuda_bf16.h>
#include <math.h>

#define NNODES 50000
#define NEDGES 800000

// ---------------- scratch (device globals: allocation-free) ----------------
__device__ int   g_cnt[NNODES];
__device__ int   g_cursor[NNODES];
__device__ int   g_rowptr[NNODES + 1];
__device__ int   g_colp[NEDGES];
__device__ float g_simp[NEDGES];
__device__ float g_invn[NNODES];
__device__ float g_invrs[NNODES];
__device__ float g_wself[NNODES];
__device__ float g_z [NNODES * 256];
__device__ float g_h1[NNODES * 256];
__device__ float g_h2[NNODES * 256];
__device__ float g_B [256 * 256];
__device__ __nv_bfloat16 g_xbf[NNODES * 256];

// ---------------- CSR build ----------------
__global__ void zero_cnt_kernel() {
    int i = blockIdx.x * blockDim.x + threadIdx.x;
    if (i < NNODES) g_cnt[i] = 0;
}

__global__ void hist_kernel(const int* __restrict__ row) {
    int e = blockIdx.x * blockDim.x + threadIdx.x;
    if (e < NEDGES) atomicAdd(&g_cnt[row[e]], 1);
}

__global__ void scan_kernel() {
    __shared__ int wsum[32];
    __shared__ int carry;
    int tid = threadIdx.x, lane = tid & 31, wid = tid >> 5;
    if (tid == 0) { carry = 0; g_rowptr[0] = 0; }
    __syncthreads();
    for (int base = 0; base < NNODES; base += 1024) {
        int i = base + tid;
        int v = (i < NNODES) ? g_cnt[i] : 0;
        int s = v;
        #pragma unroll
        for (int o = 1; o < 32; o <<= 1) {
            int t = __shfl_up_sync(0xffffffffu, s, o);
            if (lane >= o) s += t;
        }
        if (lane == 31) wsum[wid] = s;
        __syncthreads();
        if (wid == 0) {
            int ws = wsum[lane];
            #pragma unroll
            for (int o = 1; o < 32; o <<= 1) {
                int t = __shfl_up_sync(0xffffffffu, ws, o);
                if (lane >= o) ws += t;
            }
            wsum[lane] = ws;
        }
        __syncthreads();
        int incl = s + (wid ? wsum[wid - 1] : 0) + carry;
        if (i < NNODES) { g_rowptr[i + 1] = incl; g_cursor[i] = incl - v; }
        __syncthreads();
        if (tid == 1023) carry = incl;
        __syncthreads();
    }
}

__global__ void scatter_kernel(const int* __restrict__ row, const int* __restrict__ col) {
    int e = blockIdx.x * blockDim.x + threadIdx.x;
    if (e >= NEDGES) return;
    int r = row[e];
    int pos = atomicAdd(&g_cursor[r], 1);
    g_colp[pos] = col[e];
}

// ---------------- per-layer kernels ----------------
// repack W[h, d, o] -> B[d, h*HID+o]  (dense [D x Hout] row-major)
__global__ void repack_kernel(const float* __restrict__ W, int D, int Hout, int HIDp) {
    int idx = blockIdx.x * blockDim.x + threadIdx.x;
    if (idx >= D * Hout) return;
    int d = idx / Hout, c = idx % Hout;
    int h = c / HIDp, o = c % HIDp;
    g_B[idx] = W[((size_t)h * D + d) * HIDp + o];
}

// fp32 -> bf16 copy of the feature table (8 elements per thread)
__global__ void tobf16_kernel(const float* __restrict__ x, int nelem8) {
    int i = blockIdx.x * blockDim.x + threadIdx.x;
    if (i >= nelem8) return;
    const float4* xp = (const float4*)x;
    float4 a = xp[2 * i], b = xp[2 * i + 1];
    __nv_bfloat162 p0 = __float22bfloat162_rn(make_float2(a.x, a.y));
    __nv_bfloat162 p1 = __float22bfloat162_rn(make_float2(a.z, a.w));
    __nv_bfloat162 p2 = __float22bfloat162_rn(make_float2(b.x, b.y));
    __nv_bfloat162 p3 = __float22bfloat162_rn(make_float2(b.z, b.w));
    uint4 v;
    v.x = *(unsigned*)&p0; v.y = *(unsigned*)&p1;
    v.z = *(unsigned*)&p2; v.w = *(unsigned*)&p3;
    ((uint4*)g_xbf)[i] = v;
}

// 1 / max(||x_n||, 1e-12), warp per node
__global__ void invn_kernel(const float* __restrict__ x, int D) {
    int n = (blockIdx.x * blockDim.x + threadIdx.x) >> 5;
    int lane = threadIdx.x & 31;
    if (n >= NNODES) return;
    const float4* xr = (const float4*)(x + (size_t)n * D);
    int nq = D >> 2;
    float s = 0.f;
    for (int j = lane; j < nq; j += 32) {
        float4 a = xr[j];
        s += a.x * a.x + a.y * a.y + a.z * a.z + a.w * a.w;
    }
    #pragma unroll
    for (int o = 16; o; o >>= 1) s += __shfl_xor_sync(0xffffffffu, s, o);
    if (lane == 0) g_invn[n] = 1.f / fmaxf(sqrtf(s), 1e-12f);
}

// Row-stationary sim with bf16 prefilter + exact fp32 recheck.
// Warp per node; lane owns the contiguous chunk [lane*C, lane*C+C) of the row
// (C = D/32), so every warp-wide load is fully coalesced. The bf16 approx
// cosine has deterministic error <= 2^-9 (Cauchy-Schwarz), so edges with
// approx < 0.1 - 0.003 are provably below threshold; the rest are recomputed
// in pure fp32 (decision + stored value identical to the all-fp32 kernel).
template <int D>
__global__ void sim_filter_kernel(const float* __restrict__ x) {
    constexpr int C = D / 32;   // 4 (D=128) or 8 (D=256)
    int n = (blockIdx.x * blockDim.x + threadIdx.x) >> 5;
    int lane = threadIdx.x & 31;
    if (n >= NNODES) return;

    float r[C];
    {
        const float4* xr4 = (const float4*)(x + (size_t)n * D + lane * C);
        float4 a = xr4[0];
        r[0] = a.x; r[1] = a.y; r[2] = a.z; r[3] = a.w;
        if (C == 8) {
            float4 b = xr4[1];
            r[4] = b.x; r[5] = b.y; r[6] = b.z; r[7] = b.w;
        }
    }
    float invn_n = g_invn[n];
    int i1 = g_rowptr[n + 1];
    for (int i = g_rowptr[n]; i < i1; ++i) {
        int c = g_colp[i];
        float inv_c = g_invn[c];
        // --- bf16 approximate dot (half traffic) ---
        float s = 0.f;
        if (C == 4) {
            uint2 v = *(const uint2*)(g_xbf + (size_t)c * D + lane * 4);
            float2 f0 = __bfloat1622float2(*(__nv_bfloat162*)&v.x);
            float2 f1 = __bfloat1622float2(*(__nv_bfloat162*)&v.y);
            s = r[0] * f0.x + r[1] * f0.y + r[2] * f1.x + r[3] * f1.y;
        } else {
            uint4 v = *(const uint4*)(g_xbf + (size_t)c * D + lane * 8);
            float2 f0 = __bfloat1622float2(*(__nv_bfloat162*)&v.x);
            float2 f1 = __bfloat1622float2(*(__nv_bfloat162*)&v.y);
            float2 f2 = __bfloat1622float2(*(__nv_bfloat162*)&v.z);
            float2 f3 = __bfloat1622float2(*(__nv_bfloat162*)&v.w);
            s = r[0] * f0.x + r[1] * f0.y + r[2] * f1.x + r[3] * f1.y
              + r[4] * f2.x + r[5] * f2.y + r[6] * f3.x + r[7] * f3.y;
        }
        #pragma unroll
        for (int o = 16; o; o >>= 1) s += __shfl_xor_sync(0xffffffffu, s, o);
        s *= invn_n * inv_c;

        if (s < 0.1f - 0.003f) {            // provably below threshold
            if (lane == 0) g_simp[i] = 0.f;
        } else {
            // --- exact fp32 recheck (same decision rule as pure-fp32 kernel) ---
            const float4* xc4 = (const float4*)(x + (size_t)c * D + lane * C);
            float4 a = xc4[0];
            float t = r[0] * a.x + r[1] * a.y + r[2] * a.z + r[3] * a.w;
            if (C == 8) {
                float4 b = xc4[1];
                t += r[4] * b.x + r[5] * b.y + r[6] * b.z + r[7] * b.w;
            }
            #pragma unroll
            for (int o = 16; o; o >>= 1) t += __shfl_xor_sync(0xffffffffu, t, o);
            t *= invn_n * inv_c;
            if (lane == 0) g_simp[i] = (t < 0.1f) ? 0.f : t;
        }
    }
}

// rowsum / degree / self weight, warp per node
__global__ void rownorm_kernel() {
    int n = (blockIdx.x * blockDim.x + threadIdx.x) >> 5;
    int lane = threadIdx.x & 31;
    if (n >= NNODES) return;
    int s0 = g_rowptr[n], s1 = g_rowptr[n + 1];
    float sum = 0.f;
    int cnt = 0;
    for (int i = s0 + lane; i < s1; i += 32) {
        float v = g_simp[i];
        sum += v;                 // v >= 0 (thresholded cosine), so |v| == v
        cnt += (v != 0.f);
    }
    #pragma unroll
    for (int o = 16; o; o >>= 1) {
        sum += __shfl_xor_sync(0xffffffffu, sum, o);
        cnt += __shfl_xor_sync(0xffffffffu, cnt, o);
    }
    if (lane == 0) {
        g_invrs[n] = (sum > 0.f) ? 1.f / sum : 0.f;
        g_wself[n] = expf(1.f / ((float)cnt + 1.f));
    }
}

// ---------------- 3xTF32 tensor-core GEMM (fp32-accurate) ----------------
__device__ __forceinline__ unsigned f2tf32(float f) {
    unsigned r;
    asm("cvt.rna.tf32.f32 %0, %1;" : "=r"(r) : "f"(f));
    return r;
}

__device__ __forceinline__ void mma_tf32(float c[4], unsigned a0, unsigned a1,
                                         unsigned a2, unsigned a3,
                                         unsigned b0, unsigned b1) {
    asm volatile(
        "mma.sync.aligned.m16n8k8.row.col.f32.tf32.tf32.f32 "
        "{%0,%1,%2,%3}, {%4,%5,%6,%7}, {%8,%9}, {%0,%1,%2,%3};"
        : "+f"(c[0]), "+f"(c[1]), "+f"(c[2]), "+f"(c[3])
        : "r"(a0), "r"(a1), "r"(a2), "r"(a3), "r"(b0), "r"(b1));
}

// C[M, Nc] = A[M, K] * B[K, Nc], BM=128 BN=64 BK=16, 8 warps (warp tile 32x32)
__global__ void __launch_bounds__(256)
mma_gemm_kernel(const float* __restrict__ A, const float* __restrict__ Bw,
                float* __restrict__ C, int M, int K, int Nc) {
    __shared__ unsigned AsHi[128][20];
    __shared__ unsigned AsLo[128][20];
    __shared__ unsigned BsHi[16][68];
    __shared__ unsigned BsLo[16][68];

    int tid = threadIdx.x;
    int lane = tid & 31, w = tid >> 5;
    int wm = w & 3, wn = w >> 2;       // 4 warps in M, 2 in N
    int g = lane >> 2, t = lane & 3;
    int rb = blockIdx.y * 128, cb = blockIdx.x * 64;

    float acc[2][4][4];
    #pragma unroll
    for (int mi = 0; mi < 2; mi++)
        #pragma unroll
        for (int ni = 0; ni < 4; ni++)
            #pragma unroll
            for (int j = 0; j < 4; j++) acc[mi][ni][j] = 0.f;

    for (int k0 = 0; k0 < K; k0 += 16) {
        // A tile 128x16 -> 512 float4, 2 per thread
        #pragma unroll
        for (int f = tid; f < 512; f += 256) {
            int r = f >> 2, kq = f & 3;
            int gr = rb + r;
            float4 v = make_float4(0.f, 0.f, 0.f, 0.f);
            if (gr < M) v = *(const float4*)&A[(size_t)gr * K + k0 + kq * 4];
            float vv[4] = {v.x, v.y, v.z, v.w};
            #pragma unroll
            for (int j = 0; j < 4; j++) {
                unsigned hi = f2tf32(vv[j]);
                AsHi[r][kq * 4 + j] = hi;
                AsLo[r][kq * 4 + j] = f2tf32(vv[j] - __uint_as_float(hi));
            }
        }
        // B tile 16x64 -> 256 float4, 1 per thread
        {
            int r = tid >> 4, nq = tid & 15;
            float4 v = *(const float4*)&Bw[(size_t)(k0 + r) * Nc + cb + nq * 4];
            float vv[4] = {v.x, v.y, v.z, v.w};
            #pragma unroll
            for (int j = 0; j < 4; j++) {
                unsigned hi = f2tf32(vv[j]);
                BsHi[r][nq * 4 + j] = hi;
                BsLo[r][nq * 4 + j] = f2tf32(vv[j] - __uint_as_float(hi));
            }
        }
        __syncthreads();

        #pragma unroll
        for (int kk = 0; kk < 16; kk += 8) {
            unsigned ah[2][4], al[2][4], bh[4][2], bl[4][2];
            #pragma unroll
            for (int mi = 0; mi < 2; mi++) {
                int r0 = wm * 32 + mi * 16 + g;
                ah[mi][0] = AsHi[r0][kk + t];     ah[mi][1] = AsHi[r0 + 8][kk + t];
                ah[mi][2] = AsHi[r0][kk + t + 4]; ah[mi][3] = AsHi[r0 + 8][kk + t + 4];
                al[mi][0] = AsLo[r0][kk + t];     al[mi][1] = AsLo[r0 + 8][kk + t];
                al[mi][2] = AsLo[r0][kk + t + 4]; al[mi][3] = AsLo[r0 + 8][kk + t + 4];
            }
            #pragma unroll
            for (int ni = 0; ni < 4; ni++) {
                int c0 = wn * 32 + ni * 8 + g;
                bh[ni][0] = BsHi[kk + t][c0]; bh[ni][1] = BsHi[kk + t + 4][c0];
                bl[ni][0] = BsLo[kk + t][c0]; bl[ni][1] = BsLo[kk + t + 4][c0];
            }
            #pragma unroll
            for (int mi = 0; mi < 2; mi++)
                #pragma unroll
                for (int ni = 0; ni < 4; ni++) {
                    // 3xTF32: hi*hi + hi*lo + lo*hi ~= fp32 product
                    mma_tf32(acc[mi][ni], ah[mi][0], ah[mi][1], ah[mi][2], ah[mi][3],
                             bh[ni][0], bh[ni][1]);
                    mma_tf32(acc[mi][ni], ah[mi][0], ah[mi][1], ah[mi][2], ah[mi][3],
                             bl[ni][0], bl[ni][1]);
                    mma_tf32(acc[mi][ni], al[mi][0], al[mi][1], al[mi][2], al[mi][3],
                             bh[ni][0], bh[ni][1]);
                }
        }
        __syncthreads();
    }

    #pragma unroll
    for (int mi = 0; mi < 2; mi++) {
        int row = rb + wm * 32 + mi * 16 + g;
        #pragma unroll
        for (int ni = 0; ni < 4; ni++) {
            int colc = cb + wn * 32 + ni * 8 + 2 * t;
            if (row < M)
                *(float2*)&C[(size_t)row * Nc + colc] =
                    make_float2(acc[mi][ni][0], acc[mi][ni][1]);
            if (row + 8 < M)
                *(float2*)&C[(size_t)(row + 8) * Nc + colc] =
                    make_float2(acc[mi][ni][2], acc[mi][ni][3]);
        }
    }
}

// plain tiled SGEMM (kept for the tiny N=16 final projection)
template <int BM, int BN, int BK, int TM, int TN>
__global__ void __launch_bounds__(256)
sgemm_kernel(const float* __restrict__ A, const float* __restrict__ Bw,
             float* __restrict__ C, int M, int K, int Nc) {
    static_assert((BM / TM) * (BN / TN) == 256, "grid of 256 threads");
    __shared__ float As[BK][BM + 4];
    __shared__ float Bs[BK][BN];
    constexpr int TCOLS = BN / TN;
    int tid = threadIdx.x;
    int tr = tid / TCOLS, tc = tid % TCOLS;
    int rb = blockIdx.y * BM, cb = blockIdx.x * BN;
    float acc[TM][TN];
    #pragma unroll
    for (int i = 0; i < TM; i++)
        #pragma unroll
        for (int j = 0; j < TN; j++) acc[i][j] = 0.f;

    for (int k0 = 0; k0 < K; k0 += BK) {
        for (int idx = tid; idx < BM * BK; idx += 256) {
            int r = idx / BK, c = idx % BK;
            int gr = rb + r;
            As[c][r] = (gr < M) ? A[(size_t)gr * K + k0 + c] : 0.f;
        }
        for (int idx = tid; idx < BK * BN; idx += 256) {
            int r = idx / BN, c = idx % BN;
            Bs[r][c] = Bw[(size_t)(k0 + r) * Nc + cb + c];
        }
        __syncthreads();
        #pragma unroll
        for (int k = 0; k < BK; k++) {
            float a[TM], b[TN];
            #pragma unroll
            for (int i = 0; i < TM; i++) a[i] = As[k][tr * TM + i];
            #pragma unroll
            for (int j = 0; j < TN; j++) b[j] = Bs[k][tc * TN + j];
            #pragma unroll
            for (int i = 0; i < TM; i++)
                #pragma unroll
                for (int j = 0; j < TN; j++) acc[i][j] += a[i] * b[j];
        }
        __syncthreads();
    }
    #pragma unroll
    for (int i = 0; i < TM; i++) {
        int gr = rb + tr * TM + i;
        if (gr < M) {
            #pragma unroll
            for (int j = 0; j < TN; j++)
                C[(size_t)gr * Nc + cb + tc * TN + j] = acc[i][j];
        }
    }
}

// aggregation, Hout = 256: warp per node, lane owns 4+4 contiguous cols
__global__ void agg256_kernel(const float* __restrict__ z, float* __restrict__ out, int act) {
    int n = (blockIdx.x * blockDim.x + threadIdx.x) >> 5;
    int lane = threadIdx.x & 31;
    if (n >= NNODES) return;
    const float4* zr = (const float4*)(z + (size_t)n * 256);
    float ws = g_wself[n];
    float4 a0 = zr[lane], a1 = zr[32 + lane];
    a0.x *= ws; a0.y *= ws; a0.z *= ws; a0.w *= ws;
    a1.x *= ws; a1.y *= ws; a1.z *= ws; a1.w *= ws;
    float irs = g_invrs[n];
    int s1 = g_rowptr[n + 1];
    for (int i = g_rowptr[n]; i < s1; ++i) {
        float sv = g_simp[i];
        if (sv == 0.f) continue;
        float w = expf(sv * irs);
        const float4* zc = (const float4*)(z + (size_t)g_colp[i] * 256);
        float4 b0 = zc[lane], b1 = zc[32 + lane];
        a0.x += w * b0.x; a0.y += w * b0.y; a0.z += w * b0.z; a0.w += w * b0.w;
        a1.x += w * b1.x; a1.y += w * b1.y; a1.z += w * b1.z; a1.w += w * b1.w;
    }
    if (act) {
        a0.x = a0.x > 0.f ? a0.x : 0.01f * a0.x;
        a0.y = a0.y > 0.f ? a0.y : 0.01f * a0.y;
        a0.z = a0.z > 0.f ? a0.z : 0.01f * a0.z;
        a0.w = a0.w > 0.f ? a0.w : 0.01f * a0.w;
        a1.x = a1.x > 0.f ? a1.x : 0.01f * a1.x;
        a1.y = a1.y > 0.f ? a1.y : 0.01f * a1.y;
        a1.z = a1.z > 0.f ? a1.z : 0.01f * a1.z;
        a1.w = a1.w > 0.f ? a1.w : 0.01f * a1.w;
    }
    float4* o = (float4*)(out + (size_t)n * 256);
    o[lane] = a0; o[32 + lane] = a1;
}

// aggregation, Hout = 16 (final layer, no activation)
__global__ void agg16_kernel(const float* __restrict__ z, float* __restrict__ out) {
    int n = (blockIdx.x * blockDim.x + threadIdx.x) >> 5;
    int lane = threadIdx.x & 31;
    if (n >= NNODES || lane >= 16) return;
    float acc = g_wself[n] * z[(size_t)n * 16 + lane];
    float irs = g_invrs[n];
    int s1 = g_rowptr[n + 1];
    for (int i = g_rowptr[n]; i < s1; ++i) {
        float sv = g_simp[i];
        if (sv == 0.f) continue;
        acc += expf(sv * irs) * z[(size_t)g_colp[i] * 16 + lane];
    }
    out[(size_t)n * 16 + lane] = acc;
}

// ---------------- host side ----------------
static void run_layer(const float* xin, int D, const float* W, int HIDp, int Hout,
                      float* outp, bool act, float* zp) {
    repack_kernel<<<(D * Hout + 255) / 256, 256>>>(W, D, Hout, HIDp);
    invn_kernel<<<(NNODES + 7) / 8, 256>>>(xin, D);
    int nelem8 = NNODES * D / 8;
    tobf16_kernel<<<(nelem8 + 255) / 256, 256>>>(xin, nelem8);
    if (D == 128) sim_filter_kernel<128><<<(NNODES + 7) / 8, 256>>>(xin);
    else          sim_filter_kernel<256><<<(NNODES + 7) / 8, 256>>>(xin);
    rownorm_kernel<<<(NNODES + 7) / 8, 256>>>();
    float* Bdev;
    cudaGetSymbolAddress((void**)&Bdev, g_B);
    if (Hout == 256) {
        dim3 grid(256 / 64, (NNODES + 127) / 128);
        mma_gemm_kernel<<<grid, 256>>>(xin, Bdev, zp, NNODES, D, 256);
        agg256_kernel<<<(NNODES + 7) / 8, 256>>>(zp, outp, act ? 1 : 0);
    } else {
        dim3 grid(1, (NNODES + 63) / 64);
        sgemm_kernel<64, 16, 16, 4, 1><<<grid, 256>>>(xin, Bdev, zp, NNODES, D, 16);
        agg16_kernel<<<(NNODES + 7) / 8, 256>>>(zp, outp);
    }
}

extern "C" void kernel_launch(void* const* d_in, const int* in_sizes, int n_in,
                              void* d_out, int out_size) {
    const float* x  = (const float*)d_in[0];
    const float* W0 = (const float*)d_in[1];
    const float* W1 = (const float*)d_in[2];
    const float* W2 = (const float*)d_in[3];
    const int*   row = (const int*)d_in[4];
    const int*   col = (const int*)d_in[5];
    float* out = (float*)d_out;

    float *zp, *h1p, *h2p;
    cudaGetSymbolAddress((void**)&zp,  g_z);
    cudaGetSymbolAddress((void**)&h1p, g_h1);
    cudaGetSymbolAddress((void**)&h2p, g_h2);

    // CSR build (recomputed every call; deterministic work)
    zero_cnt_kernel<<<(NNODES + 255) / 256, 256>>>();
    hist_kernel<<<(NEDGES + 255) / 256, 256>>>(row);
    scan_kernel<<<1, 1024>>>();
    scatter_kernel<<<(NEDGES + 255) / 256, 256>>>(row, col);

    // layer 0: D=128, W0[4,128,64] -> h1[N,256], leaky relu
    run_layer(x,   128, W0, 64, 256, h1p, true,  zp);
    // layer 1: D=256, W1[4,256,64] -> h2[N,256], leaky relu
    run_layer(h1p, 256, W1, 64, 256, h2p, true,  zp);
    // layer 2: D=256, W2[1,256,16] -> out[N,16], no activation
    run_layer(h2p, 256, W2, 16, 16,  out, false, zp);
}

// round 9
// speedup vs baseline: 1.4729x; 1.2020x over previous
#include <cuda_runtime.h>
#include <math.h>

#define NNODES 50000
#define NEDGES 800000

// ---------------- scratch (device globals: allocation-free) ----------------
__device__ int   g_cnt[NNODES];
__device__ int   g_cursor[NNODES];
__device__ int   g_rowptr[NNODES + 1];
__device__ int   g_colp[NEDGES];
__device__ float g_simp[NEDGES];
__device__ float g_invn[NNODES];
__device__ float g_invrs[NNODES];
__device__ float g_wself[NNODES];
__device__ float g_z [NNODES * 256];
__device__ float g_h1[NNODES * 256];
__device__ float g_h2[NNODES * 256];
__device__ float g_B [256 * 256];

// ---------------- CSR build ----------------
__global__ void zero_cnt_kernel() {
    int i = blockIdx.x * blockDim.x + threadIdx.x;
    if (i < NNODES) g_cnt[i] = 0;
}

__global__ void hist_kernel(const int* __restrict__ row) {
    int e = blockIdx.x * blockDim.x + threadIdx.x;
    if (e < NEDGES) atomicAdd(&g_cnt[row[e]], 1);
}

__global__ void scan_kernel() {
    __shared__ int wsum[32];
    __shared__ int carry;
    int tid = threadIdx.x, lane = tid & 31, wid = tid >> 5;
    if (tid == 0) { carry = 0; g_rowptr[0] = 0; }
    __syncthreads();
    for (int base = 0; base < NNODES; base += 1024) {
        int i = base + tid;
        int v = (i < NNODES) ? g_cnt[i] : 0;
        int s = v;
        #pragma unroll
        for (int o = 1; o < 32; o <<= 1) {
            int t = __shfl_up_sync(0xffffffffu, s, o);
            if (lane >= o) s += t;
        }
        if (lane == 31) wsum[wid] = s;
        __syncthreads();
        if (wid == 0) {
            int ws = wsum[lane];
            #pragma unroll
            for (int o = 1; o < 32; o <<= 1) {
                int t = __shfl_up_sync(0xffffffffu, ws, o);
                if (lane >= o) ws += t;
            }
            wsum[lane] = ws;
        }
        __syncthreads();
        int incl = s + (wid ? wsum[wid - 1] : 0) + carry;
        if (i < NNODES) { g_rowptr[i + 1] = incl; g_cursor[i] = incl - v; }
        __syncthreads();
        if (tid == 1023) carry = incl;
        __syncthreads();
    }
}

__global__ void scatter_kernel(const int* __restrict__ row, const int* __restrict__ col) {
    int e = blockIdx.x * blockDim.x + threadIdx.x;
    if (e >= NEDGES) return;
    int r = row[e];
    int pos = atomicAdd(&g_cursor[r], 1);
    g_colp[pos] = col[e];
}

// ---------------- per-layer kernels ----------------
// repack W[h, d, o] -> B[d, h*HID+o]  (dense [D x Hout] row-major)
__global__ void repack_kernel(const float* __restrict__ W, int D, int Hout, int HIDp) {
    int idx = blockIdx.x * blockDim.x + threadIdx.x;
    if (idx >= D * Hout) return;
    int d = idx / Hout, c = idx % Hout;
    int h = c / HIDp, o = c % HIDp;
    g_B[idx] = W[((size_t)h * D + d) * HIDp + o];
}

// 1 / max(||x_n||, 1e-12), warp per node
__global__ void invn_kernel(const float* __restrict__ x, int D) {
    int n = (blockIdx.x * blockDim.x + threadIdx.x) >> 5;
    int lane = threadIdx.x & 31;
    if (n >= NNODES) return;
    const float4* xr = (const float4*)(x + (size_t)n * D);
    int nq = D >> 2;
    float s = 0.f;
    for (int j = lane; j < nq; j += 32) {
        float4 a = xr[j];
        s += a.x * a.x + a.y * a.y + a.z * a.z + a.w * a.w;
    }
    #pragma unroll
    for (int o = 16; o; o >>= 1) s += __shfl_xor_sync(0xffffffffu, s, o);
    if (lane == 0) g_invn[n] = 1.f / fmaxf(sqrtf(s), 1e-12f);
}

// Row-stationary sim, 2-edge software pipeline: two independent col gathers
// and two dot/reduction chains in flight per iteration (interleaved
// butterflies halve the exposed shfl latency). Load pattern per edge is the
// same fully-coalesced warp-wide float4 pair as the R6 kernel; per-edge math
// order unchanged -> bit-identical g_simp.
__global__ void sim_row_kernel(const float* __restrict__ x, int D) {
    int n = (blockIdx.x * blockDim.x + threadIdx.x) >> 5;
    int lane = threadIdx.x & 31;
    if (n >= NNODES) return;
    const float4* xr = (const float4*)(x + (size_t)n * D);
    float4 r0 = xr[lane];
    float4 r1 = make_float4(0.f, 0.f, 0.f, 0.f);
    if (D == 256) r1 = xr[32 + lane];
    float invn_n = g_invn[n];
    int i0 = g_rowptr[n], i1 = g_rowptr[n + 1];

    int i = i0;
    for (; i + 2 <= i1; i += 2) {
        int ca = g_colp[i], cb = g_colp[i + 1];
        const float4* xa = (const float4*)(x + (size_t)ca * D);
        const float4* xb = (const float4*)(x + (size_t)cb * D);
        float4 a0 = xa[lane];
        float4 b0 = xb[lane];
        float sa = r0.x * a0.x + r0.y * a0.y + r0.z * a0.z + r0.w * a0.w;
        float sb = r0.x * b0.x + r0.y * b0.y + r0.z * b0.z + r0.w * b0.w;
        if (D == 256) {
            float4 a1 = xa[32 + lane];
            float4 b1 = xb[32 + lane];
            sa += r1.x * a1.x + r1.y * a1.y + r1.z * a1.z + r1.w * a1.w;
            sb += r1.x * b1.x + r1.y * b1.y + r1.z * b1.z + r1.w * b1.w;
        }
        #pragma unroll
        for (int o = 16; o; o >>= 1) {
            sa += __shfl_xor_sync(0xffffffffu, sa, o);
            sb += __shfl_xor_sync(0xffffffffu, sb, o);
        }
        if (lane == 0) {
            sa *= invn_n * g_invn[ca];
            sb *= invn_n * g_invn[cb];
            g_simp[i]     = (sa < 0.1f) ? 0.f : sa;
            g_simp[i + 1] = (sb < 0.1f) ? 0.f : sb;
        }
    }
    if (i < i1) {
        int c = g_colp[i];
        const float4* xc = (const float4*)(x + (size_t)c * D);
        float4 b0 = xc[lane];
        float s = r0.x * b0.x + r0.y * b0.y + r0.z * b0.z + r0.w * b0.w;
        if (D == 256) {
            float4 b1 = xc[32 + lane];
            s += r1.x * b1.x + r1.y * b1.y + r1.z * b1.z + r1.w * b1.w;
        }
        #pragma unroll
        for (int o = 16; o; o >>= 1) s += __shfl_xor_sync(0xffffffffu, s, o);
        if (lane == 0) {
            s *= invn_n * g_invn[c];
            g_simp[i] = (s < 0.1f) ? 0.f : s;
        }
    }
}

// rowsum / degree / self weight, warp per node
__global__ void rownorm_kernel() {
    int n = (blockIdx.x * blockDim.x + threadIdx.x) >> 5;
    int lane = threadIdx.x & 31;
    if (n >= NNODES) return;
    int s0 = g_rowptr[n], s1 = g_rowptr[n + 1];
    float sum = 0.f;
    int cnt = 0;
    for (int i = s0 + lane; i < s1; i += 32) {
        float v = g_simp[i];
        sum += v;                 // v >= 0 (thresholded cosine), so |v| == v
        cnt += (v != 0.f);
    }
    #pragma unroll
    for (int o = 16; o; o >>= 1) {
        sum += __shfl_xor_sync(0xffffffffu, sum, o);
        cnt += __shfl_xor_sync(0xffffffffu, cnt, o);
    }
    if (lane == 0) {
        g_invrs[n] = (sum > 0.f) ? 1.f / sum : 0.f;
        g_wself[n] = expf(1.f / ((float)cnt + 1.f));
    }
}

// ---------------- 3xTF32 tensor-core GEMM (fp32-accurate) ----------------
__device__ __forceinline__ unsigned f2tf32(float f) {
    unsigned r;
    asm("cvt.rna.tf32.f32 %0, %1;" : "=r"(r) : "f"(f));
    return r;
}

__device__ __forceinline__ void mma_tf32(float c[4], unsigned a0, unsigned a1,
                                         unsigned a2, unsigned a3,
                                         unsigned b0, unsigned b1) {
    asm volatile(
        "mma.sync.aligned.m16n8k8.row.col.f32.tf32.tf32.f32 "
        "{%0,%1,%2,%3}, {%4,%5,%6,%7}, {%8,%9}, {%0,%1,%2,%3};"
        : "+f"(c[0]), "+f"(c[1]), "+f"(c[2]), "+f"(c[3])
        : "r"(a0), "r"(a1), "r"(a2), "r"(a3), "r"(b0), "r"(b1));
}

// C[M, Nc] = A[M, K] * B[K, Nc], BM=128 BN=64 BK=16, 8 warps (warp tile 32x32)
__global__ void __launch_bounds__(256)
mma_gemm_kernel(const float* __restrict__ A, const float* __restrict__ Bw,
                float* __restrict__ C, int M, int K, int Nc) {
    __shared__ unsigned AsHi[128][20];
    __shared__ unsigned AsLo[128][20];
    __shared__ unsigned BsHi[16][68];
    __shared__ unsigned BsLo[16][68];

    int tid = threadIdx.x;
    int lane = tid & 31, w = tid >> 5;
    int wm = w & 3, wn = w >> 2;       // 4 warps in M, 2 in N
    int g = lane >> 2, t = lane & 3;
    int rb = blockIdx.y * 128, cb = blockIdx.x * 64;

    float acc[2][4][4];
    #pragma unroll
    for (int mi = 0; mi < 2; mi++)
        #pragma unroll
        for (int ni = 0; ni < 4; ni++)
            #pragma unroll
            for (int j = 0; j < 4; j++) acc[mi][ni][j] = 0.f;

    for (int k0 = 0; k0 < K; k0 += 16) {
        // A tile 128x16 -> 512 float4, 2 per thread
        #pragma unroll
        for (int f = tid; f < 512; f += 256) {
            int r = f >> 2, kq = f & 3;
            int gr = rb + r;
            float4 v = make_float4(0.f, 0.f, 0.f, 0.f);
            if (gr < M) v = *(const float4*)&A[(size_t)gr * K + k0 + kq * 4];
            float vv[4] = {v.x, v.y, v.z, v.w};
            #pragma unroll
            for (int j = 0; j < 4; j++) {
                unsigned hi = f2tf32(vv[j]);
                AsHi[r][kq * 4 + j] = hi;
                AsLo[r][kq * 4 + j] = f2tf32(vv[j] - __uint_as_float(hi));
            }
        }
        // B tile 16x64 -> 256 float4, 1 per thread
        {
            int r = tid >> 4, nq = tid & 15;
            float4 v = *(const float4*)&Bw[(size_t)(k0 + r) * Nc + cb + nq * 4];
            float vv[4] = {v.x, v.y, v.z, v.w};
            #pragma unroll
            for (int j = 0; j < 4; j++) {
                unsigned hi = f2tf32(vv[j]);
                BsHi[r][nq * 4 + j] = hi;
                BsLo[r][nq * 4 + j] = f2tf32(vv[j] - __uint_as_float(hi));
            }
        }
        __syncthreads();

        #pragma unroll
        for (int kk = 0; kk < 16; kk += 8) {
            unsigned ah[2][4], al[2][4], bh[4][2], bl[4][2];
            #pragma unroll
            for (int mi = 0; mi < 2; mi++) {
                int r0 = wm * 32 + mi * 16 + g;
                ah[mi][0] = AsHi[r0][kk + t];     ah[mi][1] = AsHi[r0 + 8][kk + t];
                ah[mi][2] = AsHi[r0][kk + t + 4]; ah[mi][3] = AsHi[r0 + 8][kk + t + 4];
                al[mi][0] = AsLo[r0][kk + t];     al[mi][1] = AsLo[r0 + 8][kk + t];
                al[mi][2] = AsLo[r0][kk + t + 4]; al[mi][3] = AsLo[r0 + 8][kk + t + 4];
            }
            #pragma unroll
            for (int ni = 0; ni < 4; ni++) {
                int c0 = wn * 32 + ni * 8 + g;
                bh[ni][0] = BsHi[kk + t][c0]; bh[ni][1] = BsHi[kk + t + 4][c0];
                bl[ni][0] = BsLo[kk + t][c0]; bl[ni][1] = BsLo[kk + t + 4][c0];
            }
            #pragma unroll
            for (int mi = 0; mi < 2; mi++)
                #pragma unroll
                for (int ni = 0; ni < 4; ni++) {
                    // 3xTF32: hi*hi + hi*lo + lo*hi ~= fp32 product
                    mma_tf32(acc[mi][ni], ah[mi][0], ah[mi][1], ah[mi][2], ah[mi][3],
                             bh[ni][0], bh[ni][1]);
                    mma_tf32(acc[mi][ni], ah[mi][0], ah[mi][1], ah[mi][2], ah[mi][3],
                             bl[ni][0], bl[ni][1]);
                    mma_tf32(acc[mi][ni], al[mi][0], al[mi][1], al[mi][2], al[mi][3],
                             bh[ni][0], bh[ni][1]);
                }
        }
        __syncthreads();
    }

    #pragma unroll
    for (int mi = 0; mi < 2; mi++) {
        int row = rb + wm * 32 + mi * 16 + g;
        #pragma unroll
        for (int ni = 0; ni < 4; ni++) {
            int colc = cb + wn * 32 + ni * 8 + 2 * t;
            if (row < M)
                *(float2*)&C[(size_t)row * Nc + colc] =
                    make_float2(acc[mi][ni][0], acc[mi][ni][1]);
            if (row + 8 < M)
                *(float2*)&C[(size_t)(row + 8) * Nc + colc] =
                    make_float2(acc[mi][ni][2], acc[mi][ni][3]);
        }
    }
}

// plain tiled SGEMM (kept for the tiny N=16 final projection)
template <int BM, int BN, int BK, int TM, int TN>
__global__ void __launch_bounds__(256)
sgemm_kernel(const float* __restrict__ A, const float* __restrict__ Bw,
             float* __restrict__ C, int M, int K, int Nc) {
    static_assert((BM / TM) * (BN / TN) == 256, "grid of 256 threads");
    __shared__ float As[BK][BM + 4];
    __shared__ float Bs[BK][BN];
    constexpr int TCOLS = BN / TN;
    int tid = threadIdx.x;
    int tr = tid / TCOLS, tc = tid % TCOLS;
    int rb = blockIdx.y * BM, cb = blockIdx.x * BN;
    float acc[TM][TN];
    #pragma unroll
    for (int i = 0; i < TM; i++)
        #pragma unroll
        for (int j = 0; j < TN; j++) acc[i][j] = 0.f;

    for (int k0 = 0; k0 < K; k0 += BK) {
        for (int idx = tid; idx < BM * BK; idx += 256) {
            int r = idx / BK, c = idx % BK;
            int gr = rb + r;
            As[c][r] = (gr < M) ? A[(size_t)gr * K + k0 + c] : 0.f;
        }
        for (int idx = tid; idx < BK * BN; idx += 256) {
            int r = idx / BN, c = idx % BN;
            Bs[r][c] = Bw[(size_t)(k0 + r) * Nc + cb + c];
        }
        __syncthreads();
        #pragma unroll
        for (int k = 0; k < BK; k++) {
            float a[TM], b[TN];
            #pragma unroll
            for (int i = 0; i < TM; i++) a[i] = As[k][tr * TM + i];
            #pragma unroll
            for (int j = 0; j < TN; j++) b[j] = Bs[k][tc * TN + j];
            #pragma unroll
            for (int i = 0; i < TM; i++)
                #pragma unroll
                for (int j = 0; j < TN; j++) acc[i][j] += a[i] * b[j];
        }
        __syncthreads();
    }
    #pragma unroll
    for (int i = 0; i < TM; i++) {
        int gr = rb + tr * TM + i;
        if (gr < M) {
            #pragma unroll
            for (int j = 0; j < TN; j++)
                C[(size_t)gr * Nc + cb + tc * TN + j] = acc[i][j];
        }
    }
}

// aggregation, Hout = 256: warp per node, lane owns 4+4 contiguous cols
__global__ void agg256_kernel(const float* __restrict__ z, float* __restrict__ out, int act) {
    int n = (blockIdx.x * blockDim.x + threadIdx.x) >> 5;
    int lane = threadIdx.x & 31;
    if (n >= NNODES) return;
    const float4* zr = (const float4*)(z + (size_t)n * 256);
    float ws = g_wself[n];
    float4 a0 = zr[lane], a1 = zr[32 + lane];
    a0.x *= ws; a0.y *= ws; a0.z *= ws; a0.w *= ws;
    a1.x *= ws; a1.y *= ws; a1.z *= ws; a1.w *= ws;
    float irs = g_invrs[n];
    int s1 = g_rowptr[n + 1];
    for (int i = g_rowptr[n]; i < s1; ++i) {
        float sv = g_simp[i];
        if (sv == 0.f) continue;
        float w = expf(sv * irs);
        const float4* zc = (const float4*)(z + (size_t)g_colp[i] * 256);
        float4 b0 = zc[lane], b1 = zc[32 + lane];
        a0.x += w * b0.x; a0.y += w * b0.y; a0.z += w * b0.z; a0.w += w * b0.w;
        a1.x += w * b1.x; a1.y += w * b1.y; a1.z += w * b1.z; a1.w += w * b1.w;
    }
    if (act) {
        a0.x = a0.x > 0.f ? a0.x : 0.01f * a0.x;
        a0.y = a0.y > 0.f ? a0.y : 0.01f * a0.y;
        a0.z = a0.z > 0.f ? a0.z : 0.01f * a0.z;
        a0.w = a0.w > 0.f ? a0.w : 0.01f * a0.w;
        a1.x = a1.x > 0.f ? a1.x : 0.01f * a1.x;
        a1.y = a1.y > 0.f ? a1.y : 0.01f * a1.y;
        a1.z = a1.z > 0.f ? a1.z : 0.01f * a1.z;
        a1.w = a1.w > 0.f ? a1.w : 0.01f * a1.w;
    }
    float4* o = (float4*)(out + (size_t)n * 256);
    o[lane] = a0; o[32 + lane] = a1;
}

// aggregation, Hout = 16 (final layer, no activation)
__global__ void agg16_kernel(const float* __restrict__ z, float* __restrict__ out) {
    int n = (blockIdx.x * blockDim.x + threadIdx.x) >> 5;
    int lane = threadIdx.x & 31;
    if (n >= NNODES || lane >= 16) return;
    float acc = g_wself[n] * z[(size_t)n * 16 + lane];
    float irs = g_invrs[n];
    int s1 = g_rowptr[n + 1];
    for (int i = g_rowptr[n]; i < s1; ++i) {
        float sv = g_simp[i];
        if (sv == 0.f) continue;
        acc += expf(sv * irs) * z[(size_t)g_colp[i] * 16 + lane];
    }
    out[(size_t)n * 16 + lane] = acc;
}

// ---------------- host side ----------------
static void run_layer(const float* xin, int D, const float* W, int HIDp, int Hout,
                      float* outp, bool act, float* zp) {
    repack_kernel<<<(D * Hout + 255) / 256, 256>>>(W, D, Hout, HIDp);
    invn_kernel<<<(NNODES + 7) / 8, 256>>>(xin, D);
    sim_row_kernel<<<(NNODES + 7) / 8, 256>>>(xin, D);
    rownorm_kernel<<<(NNODES + 7) / 8, 256>>>();
    float* Bdev;
    cudaGetSymbolAddress((void**)&Bdev, g_B);
    if (Hout == 256) {
        dim3 grid(256 / 64, (NNODES + 127) / 128);
        mma_gemm_kernel<<<grid, 256>>>(xin, Bdev, zp, NNODES, D, 256);
        agg256_kernel<<<(NNODES + 7) / 8, 256>>>(zp, outp, act ? 1 : 0);
    } else {
        dim3 grid(1, (NNODES + 63) / 64);
        sgemm_kernel<64, 16, 16, 4, 1><<<grid, 256>>>(xin, Bdev, zp, NNODES, D, 16);
        agg16_kernel<<<(NNODES + 7) / 8, 256>>>(zp, outp);
    }
}

extern "C" void kernel_launch(void* const* d_in, const int* in_sizes, int n_in,
                              void* d_out, int out_size) {
    const float* x  = (const float*)d_in[0];
    const float* W0 = (const float*)d_in[1];
    const float* W1 = (const float*)d_in[2];
    const float* W2 = (const float*)d_in[3];
    const int*   row = (const int*)d_in[4];
    const int*   col = (const int*)d_in[5];
    float* out = (float*)d_out;

    float *zp, *h1p, *h2p;
    cudaGetSymbolAddress((void**)&zp,  g_z);
    cudaGetSymbolAddress((void**)&h1p, g_h1);
    cudaGetSymbolAddress((void**)&h2p, g_h2);

    // CSR build (recomputed every call; deterministic work)
    zero_cnt_kernel<<<(NNODES + 255) / 256, 256>>>();
    hist_kernel<<<(NEDGES + 255) / 256, 256>>>(row);
    scan_kernel<<<1, 1024>>>();
    scatter_kernel<<<(NEDGES + 255) / 256, 256>>>(row, col);

    // layer 0: D=128, W0[4,128,64] -> h1[N,256], leaky relu
    run_layer(x,   128, W0, 64, 256, h1p, true,  zp);
    // layer 1: D=256, W1[4,256,64] -> h2[N,256], leaky relu
    run_layer(h1p, 256, W1, 64, 256, h2p, true,  zp);
    // layer 2: D=256, W2[1,256,16] -> out[N,16], no activation
    run_layer(h2p, 256, W2, 16, 16,  out, false, zp);
}